// round 10
// baseline (speedup 1.0000x reference)
#include <cuda_runtime.h>

// Problem constants
#define TAU_SYN_INV 0.5f
#define TAU_MEM_INV 0.5f
#define V_TH        1.0f
#define V_RESET     0.0f
#define INHIB      (-5.0f)

constexpr int N_COLS  = 8192;
constexpr int THREADS = 512;
constexpr int NVEC    = N_COLS / 4;            // 2048 float4 per row
constexpr int ITERS   = NVEC / THREADS;        // 4 float4 per thread
constexpr int NWARPS  = THREADS / 32;          // 16
constexpr int GRID    = 296;                   // 2 persistent CTAs per SM (148 SMs)

// Argmax key: high 32 bits = float bits of v_new (v_new >= 1.0 > 0 so positive-float
// ordering is monotone in the bit pattern), low 32 bits = ~idx (first-index tie-break
// under unsigned max). key==0 means "no spike".
__device__ __forceinline__ unsigned long long make_key(float v, int idx) {
    return ((unsigned long long)__float_as_uint(v) << 32) | (unsigned int)(~idx);
}

__global__ __launch_bounds__(THREADS, 2)
void lif_wta_kernel(const float4* __restrict__ x,
                    const float4* __restrict__ vmem,
                    const float4* __restrict__ isyn,
                    float4* __restrict__ z_out,
                    float4* __restrict__ v_out,
                    float4* __restrict__ i_out,
                    int B)
{
    const int tid = threadIdx.x;
    __shared__ unsigned long long s_w[NWARPS];

    for (int row = blockIdx.x; row < B; row += GRID) {
        const size_t base = (size_t)row * NVEC;
        unsigned long long key = 0ULL;

        // ---- Phase 1: compute, stream z and i_new, local packed argmax ----
        #pragma unroll
        for (int it = 0; it < ITERS; it++) {
            const int c = tid + it * THREADS;
            const float4 xv = x[base + c];
            const float4 vv = vmem[base + c];
            const float4 iv = isyn[base + c];

            float4 in4, z4;
            const float* xp = (const float*)&xv;
            const float* vp = (const float*)&vv;
            const float* ip = (const float*)&iv;
            float* inp = (float*)&in4;
            float* zp  = (float*)&z4;

            #pragma unroll
            for (int j = 0; j < 4; j++) {
                const float i_new = ip[j] + TAU_SYN_INV * (xp[j] - ip[j]);
                const float v_new = vp[j] + TAU_MEM_INV * (i_new - vp[j]);
                const bool  spike = (v_new >= V_TH);
                inp[j] = i_new;
                zp[j]  = spike ? 1.0f : 0.0f;
                if (spike) {
                    const unsigned long long k = make_key(v_new, c * 4 + j);
                    if (k > key) key = k;
                }
            }
            i_out[base + c] = in4;
            z_out[base + c] = z4;
        }

        // ---- Warp reduction (u64 max) ----
        #pragma unroll
        for (int off = 16; off > 0; off >>= 1) {
            const unsigned long long o = __shfl_down_sync(0xFFFFFFFFu, key, off);
            if (o > key) key = o;
        }

        // Barrier: ensure previous row's s_w consumers are done before overwrite.
        __syncthreads();
        if ((tid & 31) == 0) s_w[tid >> 5] = key;
        __syncthreads();

        // ---- Final reduction: every thread redundantly maxes the 16 entries ----
        unsigned long long fk = s_w[0];
        #pragma unroll
        for (int w = 1; w < NWARPS; w++) {
            const unsigned long long o = s_w[w];
            if (o > fk) fk = o;
        }
        const bool any_spike = (fk != 0ULL);
        const int  winner    = ~(unsigned int)fk;   // valid only if any_spike

        // ---- Phase 2: write v_out ----
        if (any_spike) {
            // Winner-take-all: winner gets V_RESET (it spiked), rest get INHIB.
            #pragma unroll
            for (int it = 0; it < ITERS; it++) {
                const int c = tid + it * THREADS;
                float4 o;
                o.x = INHIB; o.y = INHIB; o.z = INHIB; o.w = INHIB;
                const int b4 = c * 4;
                if (winner >= b4 && winner < b4 + 4) {
                    ((float*)&o)[winner - b4] = V_RESET;
                }
                v_out[base + c] = o;
            }
        } else {
            // No spikes in row (astronomically rare): recompute v_new (re-reads hit L2).
            #pragma unroll
            for (int it = 0; it < ITERS; it++) {
                const int c = tid + it * THREADS;
                const float4 xv = x[base + c];
                const float4 vv = vmem[base + c];
                const float4 iv = isyn[base + c];
                float4 o;
                const float* xp = (const float*)&xv;
                const float* vp = (const float*)&vv;
                const float* ip = (const float*)&iv;
                float* op = (float*)&o;
                #pragma unroll
                for (int j = 0; j < 4; j++) {
                    const float i_new = ip[j] + TAU_SYN_INV * (xp[j] - ip[j]);
                    op[j] = vp[j] + TAU_MEM_INV * (i_new - vp[j]);
                }
                v_out[base + c] = o;
            }
        }
    }
}

extern "C" void kernel_launch(void* const* d_in, const int* in_sizes, int n_in,
                              void* d_out, int out_size) {
    const float4* x = (const float4*)d_in[0];
    const float4* v = (const float4*)d_in[1];
    const float4* i = (const float4*)d_in[2];

    const long long total = in_sizes[0];          // B * N
    const int B = (int)(total / N_COLS);
    const long long bn = (long long)B * N_COLS;

    float* out = (float*)d_out;
    float4* z_out = (float4*)(out);               // outputs in reference order: z, v_out, i_new
    float4* v_out = (float4*)(out + bn);
    float4* i_out = (float4*)(out + 2 * bn);

    const int grid = (B < GRID) ? B : GRID;
    lif_wta_kernel<<<grid, THREADS>>>(x, v, i, z_out, v_out, i_out, B);
}

// round 12
// speedup vs baseline: 1.1141x; 1.1141x over previous
#include <cuda_runtime.h>
#include <math_constants.h>

// Problem constants
#define TAU_SYN_INV 0.5f
#define TAU_MEM_INV 0.5f
#define V_TH        1.0f
#define V_RESET     0.0f
#define INHIB      (-5.0f)

constexpr int N_COLS  = 8192;
constexpr int THREADS = 256;
constexpr int NVEC    = N_COLS / 4;            // 2048 float4 per row
constexpr int ITERS   = NVEC / THREADS;        // 8 float4 per thread
constexpr int NWARPS  = THREADS / 32;          // 8

// (val, idx) argmax with first-index tie-break: prefer larger val, then smaller idx.
__device__ __forceinline__ void amax_update(float& bv, int& bi, float v, int i) {
    if (v > bv || (v == bv && i < bi)) { bv = v; bi = i; }
}

__global__ __launch_bounds__(THREADS, 4)
void lif_wta_kernel(const float4* __restrict__ x,
                    const float4* __restrict__ vmem,
                    const float4* __restrict__ isyn,
                    float4* __restrict__ z_out,
                    float4* __restrict__ v_out,
                    float4* __restrict__ i_out)
{
    const int row  = blockIdx.x;
    const size_t base = (size_t)row * NVEC;
    const int tid  = threadIdx.x;

    __shared__ float s_wval[NWARPS];
    __shared__ int   s_widx[NWARPS];
    __shared__ float s_best;
    __shared__ int   s_bidx;

    float best = -CUDART_INF_F;
    int   bidx = N_COLS;              // sentinel larger than any valid index

    // ---- Phase 1: compute, stream z and i_new, local argmax ----
    #pragma unroll
    for (int it = 0; it < ITERS; it++) {
        const int c = tid + it * THREADS;
        const float4 xv = x[base + c];
        const float4 vv = vmem[base + c];
        const float4 iv = isyn[base + c];

        float4 in4, z4;
        const float* xp = (const float*)&xv;
        const float* vp = (const float*)&vv;
        const float* ip = (const float*)&iv;
        float* inp = (float*)&in4;
        float* zp  = (float*)&z4;

        #pragma unroll
        for (int j = 0; j < 4; j++) {
            const float i_new = ip[j] + TAU_SYN_INV * (xp[j] - ip[j]);
            const float v_new = vp[j] + TAU_MEM_INV * (i_new - vp[j]);
            const bool  spike = (v_new >= V_TH);
            inp[j] = i_new;
            zp[j]  = spike ? 1.0f : 0.0f;
            if (spike) amax_update(best, bidx, v_new, c * 4 + j);
        }
        i_out[base + c] = in4;
        z_out[base + c] = z4;
    }

    // ---- Warp reduction ----
    #pragma unroll
    for (int off = 16; off > 0; off >>= 1) {
        const float ov = __shfl_down_sync(0xFFFFFFFFu, best, off);
        const int   oi = __shfl_down_sync(0xFFFFFFFFu, bidx, off);
        amax_update(best, bidx, ov, oi);
    }
    if ((tid & 31) == 0) {
        s_wval[tid >> 5] = best;
        s_widx[tid >> 5] = bidx;
    }
    __syncthreads();

    // ---- Final reduction in warp 0 (8 entries) ----
    if (tid < 32) {
        float fb = (tid < NWARPS) ? s_wval[tid] : -CUDART_INF_F;
        int   fi = (tid < NWARPS) ? s_widx[tid] : N_COLS;
        #pragma unroll
        for (int off = 4; off > 0; off >>= 1) {
            const float ov = __shfl_down_sync(0xFFFFFFFFu, fb, off);
            const int   oi = __shfl_down_sync(0xFFFFFFFFu, fi, off);
            amax_update(fb, fi, ov, oi);
        }
        if (tid == 0) { s_best = fb; s_bidx = fi; }
    }
    __syncthreads();

    const bool any_spike = (s_best > -CUDART_INF_F);   // block-uniform
    const int  winner    = s_bidx;

    // ---- Phase 2: write v_out ----
    if (any_spike) {
        // Winner-take-all row: winner gets V_RESET (it spiked), rest get INHIB.
        #pragma unroll
        for (int it = 0; it < ITERS; it++) {
            const int c = tid + it * THREADS;
            float4 o;
            o.x = INHIB; o.y = INHIB; o.z = INHIB; o.w = INHIB;
            const int b4 = c * 4;
            if (winner >= b4 && winner < b4 + 4) {
                ((float*)&o)[winner - b4] = V_RESET;
            }
            v_out[base + c] = o;
        }
    } else {
        // No spikes in row (astronomically rare): recompute v_new (re-reads hit L2).
        #pragma unroll
        for (int it = 0; it < ITERS; it++) {
            const int c = tid + it * THREADS;
            const float4 xv = x[base + c];
            const float4 vv = vmem[base + c];
            const float4 iv = isyn[base + c];
            float4 o;
            const float* xp = (const float*)&xv;
            const float* vp = (const float*)&vv;
            const float* ip = (const float*)&iv;
            float* op = (float*)&o;
            #pragma unroll
            for (int j = 0; j < 4; j++) {
                const float i_new = ip[j] + TAU_SYN_INV * (xp[j] - ip[j]);
                op[j] = vp[j] + TAU_MEM_INV * (i_new - vp[j]);
            }
            v_out[base + c] = o;
        }
    }
}

extern "C" void kernel_launch(void* const* d_in, const int* in_sizes, int n_in,
                              void* d_out, int out_size) {
    const float4* x = (const float4*)d_in[0];
    const float4* v = (const float4*)d_in[1];
    const float4* i = (const float4*)d_in[2];

    const long long total = in_sizes[0];          // B * N
    const int B = (int)(total / N_COLS);
    const long long bn = (long long)B * N_COLS;

    float* out = (float*)d_out;
    float4* z_out = (float4*)(out);               // outputs in reference order: z, v_out, i_new
    float4* v_out = (float4*)(out + bn);
    float4* i_out = (float4*)(out + 2 * bn);

    lif_wta_kernel<<<B, THREADS>>>(x, v, i, z_out, v_out, i_out);
}

// round 13
// speedup vs baseline: 1.1250x; 1.0098x over previous
#include <cuda_runtime.h>
#include <math_constants.h>

// Problem constants
#define TAU_SYN_INV 0.5f
#define TAU_MEM_INV 0.5f
#define V_TH        1.0f
#define V_RESET     0.0f
#define INHIB      (-5.0f)

constexpr int N_COLS  = 8192;
constexpr int THREADS = 512;
constexpr int NVEC    = N_COLS / 4;            // 2048 float4 per row
constexpr int ITERS   = NVEC / THREADS;        // 4 float4 per thread
constexpr int NWARPS  = THREADS / 32;          // 16

// (val, idx) argmax with first-index tie-break: prefer larger val, then smaller idx.
__device__ __forceinline__ void amax_update(float& bv, int& bi, float v, int i) {
    if (v > bv || (v == bv && i < bi)) { bv = v; bi = i; }
}

__global__ __launch_bounds__(THREADS, 2)
void lif_wta_kernel(const float4* __restrict__ x,
                    const float4* __restrict__ vmem,
                    const float4* __restrict__ isyn,
                    float4* __restrict__ z_out,
                    float4* __restrict__ v_out,
                    float4* __restrict__ i_out)
{
    const int row  = blockIdx.x;
    const size_t base = (size_t)row * NVEC;
    const int tid  = threadIdx.x;

    __shared__ float s_wval[NWARPS];
    __shared__ int   s_widx[NWARPS];
    __shared__ float s_best;
    __shared__ int   s_bidx;

    float best = -CUDART_INF_F;
    int   bidx = N_COLS;              // sentinel larger than any valid index

    // ---- Phase 1a: front-batch ALL input loads (12 independent LDG.128) ----
    float4 xv[ITERS], vv[ITERS], iv[ITERS];
    #pragma unroll
    for (int it = 0; it < ITERS; it++) {
        const int c = tid + it * THREADS;
        xv[it] = x[base + c];
        vv[it] = vmem[base + c];
        iv[it] = isyn[base + c];
    }

    // ---- Phase 1b: compute, stream z and i_new, local argmax ----
    #pragma unroll
    for (int it = 0; it < ITERS; it++) {
        const int c = tid + it * THREADS;
        float4 in4, z4;
        const float* xp = (const float*)&xv[it];
        const float* vp = (const float*)&vv[it];
        const float* ip = (const float*)&iv[it];
        float* inp = (float*)&in4;
        float* zp  = (float*)&z4;

        #pragma unroll
        for (int j = 0; j < 4; j++) {
            const float i_new = ip[j] + TAU_SYN_INV * (xp[j] - ip[j]);
            const float v_new = vp[j] + TAU_MEM_INV * (i_new - vp[j]);
            const bool  spike = (v_new >= V_TH);
            inp[j] = i_new;
            zp[j]  = spike ? 1.0f : 0.0f;
            if (spike) amax_update(best, bidx, v_new, c * 4 + j);
        }
        i_out[base + c] = in4;
        z_out[base + c] = z4;
    }

    // ---- Warp reduction ----
    #pragma unroll
    for (int off = 16; off > 0; off >>= 1) {
        const float ov = __shfl_down_sync(0xFFFFFFFFu, best, off);
        const int   oi = __shfl_down_sync(0xFFFFFFFFu, bidx, off);
        amax_update(best, bidx, ov, oi);
    }
    if ((tid & 31) == 0) {
        s_wval[tid >> 5] = best;
        s_widx[tid >> 5] = bidx;
    }
    __syncthreads();

    // ---- Final reduction in warp 0 ----
    if (tid < 32) {
        float fb = (tid < NWARPS) ? s_wval[tid] : -CUDART_INF_F;
        int   fi = (tid < NWARPS) ? s_widx[tid] : N_COLS;
        #pragma unroll
        for (int off = 8; off > 0; off >>= 1) {
            const float ov = __shfl_down_sync(0xFFFFFFFFu, fb, off);
            const int   oi = __shfl_down_sync(0xFFFFFFFFu, fi, off);
            amax_update(fb, fi, ov, oi);
        }
        if (tid == 0) { s_best = fb; s_bidx = fi; }
    }
    __syncthreads();

    const bool any_spike = (s_best > -CUDART_INF_F);   // block-uniform
    const int  winner    = s_bidx;

    // ---- Phase 2: write v_out ----
    if (any_spike) {
        // Winner-take-all row: winner gets V_RESET (it spiked), rest get INHIB.
        #pragma unroll
        for (int it = 0; it < ITERS; it++) {
            const int c = tid + it * THREADS;
            float4 o;
            o.x = INHIB; o.y = INHIB; o.z = INHIB; o.w = INHIB;
            const int b4 = c * 4;
            if (winner >= b4 && winner < b4 + 4) {
                ((float*)&o)[winner - b4] = V_RESET;
            }
            v_out[base + c] = o;
        }
    } else {
        // No spikes in row (astronomically rare): recompute v_new (re-reads hit L2).
        #pragma unroll
        for (int it = 0; it < ITERS; it++) {
            const int c = tid + it * THREADS;
            const float4 xr = x[base + c];
            const float4 vr = vmem[base + c];
            const float4 ir = isyn[base + c];
            float4 o;
            const float* xp = (const float*)&xr;
            const float* vp = (const float*)&vr;
            const float* ip = (const float*)&ir;
            float* op = (float*)&o;
            #pragma unroll
            for (int j = 0; j < 4; j++) {
                const float i_new = ip[j] + TAU_SYN_INV * (xp[j] - ip[j]);
                op[j] = vp[j] + TAU_MEM_INV * (i_new - vp[j]);
            }
            v_out[base + c] = o;
        }
    }
}

extern "C" void kernel_launch(void* const* d_in, const int* in_sizes, int n_in,
                              void* d_out, int out_size) {
    const float4* x = (const float4*)d_in[0];
    const float4* v = (const float4*)d_in[1];
    const float4* i = (const float4*)d_in[2];

    const long long total = in_sizes[0];          // B * N
    const int B = (int)(total / N_COLS);
    const long long bn = (long long)B * N_COLS;

    float* out = (float*)d_out;
    float4* z_out = (float4*)(out);               // outputs in reference order: z, v_out, i_new
    float4* v_out = (float4*)(out + bn);
    float4* i_out = (float4*)(out + 2 * bn);

    lif_wta_kernel<<<B, THREADS>>>(x, v, i, z_out, v_out, i_out);
}

// round 16
// speedup vs baseline: 1.1307x; 1.0050x over previous
#include <cuda_runtime.h>
#include <math_constants.h>

// Problem constants
#define TAU_SYN_INV 0.5f
#define TAU_MEM_INV 0.5f
#define V_TH        1.0f
#define V_RESET     0.0f
#define INHIB      (-5.0f)

constexpr int N_COLS  = 8192;
constexpr int THREADS = 512;
constexpr int NVEC    = N_COLS / 4;            // 2048 float4 per row
constexpr int ITERS   = NVEC / THREADS;        // 4 float4 per thread
constexpr int NWARPS  = THREADS / 32;          // 16

// (val, idx) argmax with first-index tie-break: prefer larger val, then smaller idx.
__device__ __forceinline__ void amax_update(float& bv, int& bi, float v, int i) {
    if (v > bv || (v == bv && i < bi)) { bv = v; bi = i; }
}

__global__ __launch_bounds__(THREADS, 2)
void lif_wta_kernel(const float4* __restrict__ x,
                    const float4* __restrict__ vmem,
                    const float4* __restrict__ isyn,
                    float4* __restrict__ z_out,
                    float4* __restrict__ v_out,
                    float4* __restrict__ i_out)
{
    const int row  = blockIdx.x;
    const size_t base = (size_t)row * NVEC;
    const int tid  = threadIdx.x;

    __shared__ float s_wval[NWARPS];
    __shared__ int   s_widx[NWARPS];
    __shared__ float s_best;
    __shared__ int   s_bidx;

    float best = -CUDART_INF_F;
    int   bidx = N_COLS;              // sentinel larger than any valid index

    // ---- Phase 1: stream ALL THREE outputs; v_out gets the INHIB fill
    // speculatively (correct for every element except the winner, in the
    // ~always-true spiked case). The INHIB stores have no dependencies and
    // issue immediately, overlapping writes with the input loads. ----
    const float4 inhib4 = make_float4(INHIB, INHIB, INHIB, INHIB);
    #pragma unroll
    for (int it = 0; it < ITERS; it++) {
        const int c = tid + it * THREADS;
        v_out[base + c] = inhib4;                 // dependency-free constant stream

        const float4 xv = x[base + c];
        const float4 vv = vmem[base + c];
        const float4 iv = isyn[base + c];

        float4 in4, z4;
        const float* xp = (const float*)&xv;
        const float* vp = (const float*)&vv;
        const float* ip = (const float*)&iv;
        float* inp = (float*)&in4;
        float* zp  = (float*)&z4;

        #pragma unroll
        for (int j = 0; j < 4; j++) {
            const float i_new = ip[j] + TAU_SYN_INV * (xp[j] - ip[j]);
            const float v_new = vp[j] + TAU_MEM_INV * (i_new - vp[j]);
            const bool  spike = (v_new >= V_TH);
            inp[j] = i_new;
            zp[j]  = spike ? 1.0f : 0.0f;
            if (spike) amax_update(best, bidx, v_new, c * 4 + j);
        }
        i_out[base + c] = in4;
        z_out[base + c] = z4;
    }

    // ---- Warp reduction ----
    #pragma unroll
    for (int off = 16; off > 0; off >>= 1) {
        const float ov = __shfl_down_sync(0xFFFFFFFFu, best, off);
        const int   oi = __shfl_down_sync(0xFFFFFFFFu, bidx, off);
        amax_update(best, bidx, ov, oi);
    }
    if ((tid & 31) == 0) {
        s_wval[tid >> 5] = best;
        s_widx[tid >> 5] = bidx;
    }
    __syncthreads();   // also orders the INHIB fill before the patch below

    // ---- Final reduction in warp 0 ----
    if (tid < 32) {
        float fb = (tid < NWARPS) ? s_wval[tid] : -CUDART_INF_F;
        int   fi = (tid < NWARPS) ? s_widx[tid] : N_COLS;
        #pragma unroll
        for (int off = 8; off > 0; off >>= 1) {
            const float ov = __shfl_down_sync(0xFFFFFFFFu, fb, off);
            const int   oi = __shfl_down_sync(0xFFFFFFFFu, fi, off);
            amax_update(fb, fi, ov, oi);
        }
        if (tid == 0) { s_best = fb; s_bidx = fi; }
    }
    __syncthreads();

    const bool any_spike = (s_best > -CUDART_INF_F);   // block-uniform
    const int  winner    = s_bidx;

    // ---- Phase 2: tiny patch (common case) or rare full rewrite ----
    if (any_spike) {
        // Winner spiked -> v_after = V_RESET. Single 4-byte store patches
        // the speculative INHIB fill; ordered after it by __syncthreads.
        if (tid == 0) {
            ((float*)&v_out[base])[winner] = V_RESET;
        }
    } else {
        // No spikes in row (probability ~e^-165): v_out = v_new unchanged.
        // Recompute from inputs (re-reads hit L2), overwriting the INHIB fill.
        #pragma unroll
        for (int it = 0; it < ITERS; it++) {
            const int c = tid + it * THREADS;
            const float4 xr = x[base + c];
            const float4 vr = vmem[base + c];
            const float4 ir = isyn[base + c];
            float4 o;
            const float* xp = (const float*)&xr;
            const float* vp = (const float*)&vr;
            const float* ip = (const float*)&ir;
            float* op = (float*)&o;
            #pragma unroll
            for (int j = 0; j < 4; j++) {
                const float i_new = ip[j] + TAU_SYN_INV * (xp[j] - ip[j]);
                op[j] = vp[j] + TAU_MEM_INV * (i_new - vp[j]);
            }
            v_out[base + c] = o;
        }
    }
}

extern "C" void kernel_launch(void* const* d_in, const int* in_sizes, int n_in,
                              void* d_out, int out_size) {
    const float4* x = (const float4*)d_in[0];
    const float4* v = (const float4*)d_in[1];
    const float4* i = (const float4*)d_in[2];

    const long long total = in_sizes[0];          // B * N
    const int B = (int)(total / N_COLS);
    const long long bn = (long long)B * N_COLS;

    float* out = (float*)d_out;
    float4* z_out = (float4*)(out);               // outputs in reference order: z, v_out, i_new
    float4* v_out = (float4*)(out + bn);
    float4* i_out = (float4*)(out + 2 * bn);

    lif_wta_kernel<<<B, THREADS>>>(x, v, i, z_out, v_out, i_out);
}

// round 17
// speedup vs baseline: 1.1416x; 1.0097x over previous
#include <cuda_runtime.h>
#include <math_constants.h>

// Problem constants
#define TAU_SYN_INV 0.5f
#define TAU_MEM_INV 0.5f
#define V_TH        1.0f
#define V_RESET     0.0f
#define INHIB      (-5.0f)

constexpr int N_COLS  = 8192;
constexpr int THREADS = 512;
constexpr int NVEC    = N_COLS / 4;            // 2048 float4 per row
constexpr int ITERS   = NVEC / THREADS;        // 4 float4 per thread
constexpr int NWARPS  = THREADS / 32;          // 16

// (val, idx) argmax with first-index tie-break: prefer larger val, then smaller idx.
__device__ __forceinline__ void amax_update(float& bv, int& bi, float v, int i) {
    if (v > bv || (v == bv && i < bi)) { bv = v; bi = i; }
}

__global__ __launch_bounds__(THREADS, 2)
void lif_wta_kernel(const float4* __restrict__ x,
                    const float4* __restrict__ vmem,
                    const float4* __restrict__ isyn,
                    float4* __restrict__ z_out,
                    float4* __restrict__ v_out,
                    float4* __restrict__ i_out)
{
    const int row  = blockIdx.x;
    const size_t base = (size_t)row * NVEC;
    const int tid  = threadIdx.x;

    __shared__ float s_wval[NWARPS];
    __shared__ int   s_widx[NWARPS];
    __shared__ float s_best;
    __shared__ int   s_bidx;

    float best = -CUDART_INF_F;
    int   bidx = N_COLS;              // sentinel larger than any valid index

    // ---- Phase 1: loads FIRST (keep the batched load front), compute, then
    // stream all three outputs. v_out gets the speculative INHIB fill — in the
    // ~always-true spiked case only the winner element needs patching later. ----
    const float4 inhib4 = make_float4(INHIB, INHIB, INHIB, INHIB);
    #pragma unroll
    for (int it = 0; it < ITERS; it++) {
        const int c = tid + it * THREADS;
        const float4 xv = x[base + c];
        const float4 vv = vmem[base + c];
        const float4 iv = isyn[base + c];

        float4 in4, z4;
        const float* xp = (const float*)&xv;
        const float* vp = (const float*)&vv;
        const float* ip = (const float*)&iv;
        float* inp = (float*)&in4;
        float* zp  = (float*)&z4;

        #pragma unroll
        for (int j = 0; j < 4; j++) {
            const float i_new = ip[j] + TAU_SYN_INV * (xp[j] - ip[j]);
            const float v_new = vp[j] + TAU_MEM_INV * (i_new - vp[j]);
            const bool  spike = (v_new >= V_TH);
            inp[j] = i_new;
            zp[j]  = spike ? 1.0f : 0.0f;
            if (spike) amax_update(best, bidx, v_new, c * 4 + j);
        }
        i_out[base + c] = in4;
        z_out[base + c] = z4;
        v_out[base + c] = inhib4;                 // speculative; patched below
    }

    // ---- Warp reduction ----
    #pragma unroll
    for (int off = 16; off > 0; off >>= 1) {
        const float ov = __shfl_down_sync(0xFFFFFFFFu, best, off);
        const int   oi = __shfl_down_sync(0xFFFFFFFFu, bidx, off);
        amax_update(best, bidx, ov, oi);
    }
    if ((tid & 31) == 0) {
        s_wval[tid >> 5] = best;
        s_widx[tid >> 5] = bidx;
    }
    __syncthreads();   // also orders the INHIB fill before the patch below

    // ---- Final reduction in warp 0 ----
    if (tid < 32) {
        float fb = (tid < NWARPS) ? s_wval[tid] : -CUDART_INF_F;
        int   fi = (tid < NWARPS) ? s_widx[tid] : N_COLS;
        #pragma unroll
        for (int off = 8; off > 0; off >>= 1) {
            const float ov = __shfl_down_sync(0xFFFFFFFFu, fb, off);
            const int   oi = __shfl_down_sync(0xFFFFFFFFu, fi, off);
            amax_update(fb, fi, ov, oi);
        }
        if (tid == 0) { s_best = fb; s_bidx = fi; }
    }
    __syncthreads();

    const bool any_spike = (s_best > -CUDART_INF_F);   // block-uniform
    const int  winner    = s_bidx;

    // ---- Phase 2: tiny patch (common case) or rare full rewrite ----
    if (any_spike) {
        // Winner spiked -> v_after = V_RESET. Single 4-byte store patches the
        // speculative INHIB fill; ordered after it by the __syncthreads above.
        if (tid == 0) {
            ((float*)&v_out[base])[winner] = V_RESET;
        }
    } else {
        // No spikes in row (probability ~e^-165): v_out = v_new unchanged.
        // Recompute from inputs (re-reads hit L2), overwriting the INHIB fill.
        #pragma unroll
        for (int it = 0; it < ITERS; it++) {
            const int c = tid + it * THREADS;
            const float4 xr = x[base + c];
            const float4 vr = vmem[base + c];
            const float4 ir = isyn[base + c];
            float4 o;
            const float* xp = (const float*)&xr;
            const float* vp = (const float*)&vr;
            const float* ip = (const float*)&ir;
            float* op = (float*)&o;
            #pragma unroll
            for (int j = 0; j < 4; j++) {
                const float i_new = ip[j] + TAU_SYN_INV * (xp[j] - ip[j]);
                op[j] = vp[j] + TAU_MEM_INV * (i_new - vp[j]);
            }
            v_out[base + c] = o;
        }
    }
}

extern "C" void kernel_launch(void* const* d_in, const int* in_sizes, int n_in,
                              void* d_out, int out_size) {
    const float4* x = (const float4*)d_in[0];
    const float4* v = (const float4*)d_in[1];
    const float4* i = (const float4*)d_in[2];

    const long long total = in_sizes[0];          // B * N
    const int B = (int)(total / N_COLS);
    const long long bn = (long long)B * N_COLS;

    float* out = (float*)d_out;
    float4* z_out = (float4*)(out);               // outputs in reference order: z, v_out, i_new
    float4* v_out = (float4*)(out + bn);
    float4* i_out = (float4*)(out + 2 * bn);

    lif_wta_kernel<<<B, THREADS>>>(x, v, i, z_out, v_out, i_out);
}